// round 5
// baseline (speedup 1.0000x reference)
#include <cuda_runtime.h>
#include <math.h>

#define S   160
#define SQ  40              // S/4 float4 quads per row
#define R   9               // 9x 3-erosion == one 19-window (clamped)
#define TY  80
#define TZ  80
#define HY  (TY + 2 * R)    // 98
#define HZ  (TZ + 2 * R)    // 98
#define NTA 640
#define NTB 640
#define NBLOCKS_B (2 * 160 * 4)   // (S/TZ) * S * 4

// Scratch (static __device__ = allowed; no allocation calls)
__device__ float        g_exy[4 * S * S * S];
__device__ double       g_acc[3];
__device__ unsigned int g_done;          // zero-initialized; reset by last block

__device__ __forceinline__ int clampi(int v, int lo, int hi) {
    return v < lo ? lo : (v > hi ? hi : v);
}
__device__ __forceinline__ float4 f4min(float4 a, float4 b) {
    return make_float4(fminf(a.x, b.x), fminf(a.y, b.y),
                       fminf(a.z, b.z), fminf(a.w, b.w));
}

// ---------------------------------------------------------------------------
// Pass A: fused 19-min over y then x. Block = (ytile, z, b), 640 threads.
// smem: A[98][40] float4 raw rows, C[80][40] float4 y-min rows (113.9 KB).
// Block (0,0,0) also zeroes the accumulators (pass B only reads them later).
// ---------------------------------------------------------------------------
__global__ void __launch_bounds__(NTA, 2) minxy_kernel(const float4* __restrict__ in4,
                                                       float4* __restrict__ out4) {
    extern __shared__ float4 sm4[];
    float4* A = sm4;               // HY*SQ
    float4* C = sm4 + HY * SQ;     // TY*SQ

    const int tid = threadIdx.x;
    const int q   = tid % SQ;
    const int g   = tid / SQ;      // 0..15
    const int y0  = blockIdx.x * TY;
    const int z   = blockIdx.y;
    const int b   = blockIdx.z;
    const long long base4 = (long long)(b * S + z) * S * SQ;

    if (blockIdx.x == 0 && blockIdx.y == 0 && blockIdx.z == 0 && tid < 3)
        g_acc[tid] = 0.0;

    // Load 98 y-rows (clamped halo), float4-coalesced.
    for (int i = tid; i < HY * SQ; i += NTA) {
        const int r = i / SQ, qq = i % SQ;
        const int y = clampi(y0 - R + r, 0, S - 1);
        A[i] = in4[base4 + y * SQ + qq];
    }
    __syncthreads();

    // y-min: each group of 4 outputs shares a 16-row tree-min core.
    for (int gg = g; gg < TY / 4; gg += 16) {
        const int o = 4 * gg;
        const float4* col = A + q;
        float4 p0 = f4min(col[(o + 3) * SQ],  col[(o + 4) * SQ]);
        float4 p1 = f4min(col[(o + 5) * SQ],  col[(o + 6) * SQ]);
        float4 p2 = f4min(col[(o + 7) * SQ],  col[(o + 8) * SQ]);
        float4 p3 = f4min(col[(o + 9) * SQ],  col[(o + 10) * SQ]);
        float4 p4 = f4min(col[(o + 11) * SQ], col[(o + 12) * SQ]);
        float4 p5 = f4min(col[(o + 13) * SQ], col[(o + 14) * SQ]);
        float4 p6 = f4min(col[(o + 15) * SQ], col[(o + 16) * SQ]);
        float4 p7 = f4min(col[(o + 17) * SQ], col[(o + 18) * SQ]);
        float4 core = f4min(f4min(f4min(p0, p1), f4min(p2, p3)),
                            f4min(f4min(p4, p5), f4min(p6, p7)));
        float4 a0 = col[(o + 0) * SQ],  a1 = col[(o + 1) * SQ];
        float4 a2 = col[(o + 2) * SQ];
        float4 b0 = col[(o + 19) * SQ], b1 = col[(o + 20) * SQ];
        float4 b2 = col[(o + 21) * SQ];
        C[(o + 0) * SQ + q] = f4min(f4min(a0, a1),   f4min(a2, core));
        C[(o + 1) * SQ + q] = f4min(f4min(a1, a2),   f4min(core, b0));
        C[(o + 2) * SQ + q] = f4min(f4min(a2, core), f4min(b0, b1));
        C[(o + 3) * SQ + q] = f4min(f4min(core, b0), f4min(b1, b2));
    }
    __syncthreads();

    // x-min: gather 7 float4 quads (quad-clamped, min-safe), tree core.
#pragma unroll
    for (int k = 0; k < (TY * SQ) / NTA; ++k) {   // 5 iterations, exact
        const int i = tid + NTA * k;
        const int row = i / SQ, qq = i % SQ;
        float v[28];
#pragma unroll
        for (int dq = -3; dq <= 3; ++dq) {
            const float4 c = C[row * SQ + clampi(qq + dq, 0, SQ - 1)];
            const int o = (dq + 3) * 4;
            v[o] = c.x; v[o + 1] = c.y; v[o + 2] = c.z; v[o + 3] = c.w;
        }
        float t0 = fminf(v[6],  v[7]),  t1 = fminf(v[8],  v[9]);
        float t2 = fminf(v[10], v[11]), t3 = fminf(v[12], v[13]);
        float t4 = fminf(v[14], v[15]), t5 = fminf(v[16], v[17]);
        float t6 = fminf(v[18], v[19]), t7 = fminf(v[20], v[21]);
        float core = fminf(fminf(fminf(t0, t1), fminf(t2, t3)),
                           fminf(fminf(t4, t5), fminf(t6, t7)));
        float4 r4;
        r4.x = fminf(core, fminf(v[3],  fminf(v[4],  v[5])));
        r4.y = fminf(core, fminf(v[4],  fminf(v[5],  v[22])));
        r4.z = fminf(core, fminf(v[5],  fminf(v[22], v[23])));
        r4.w = fminf(core, fminf(v[22], fminf(v[23], v[24])));
        out4[base4 + (long long)(y0 + row) * SQ + qq] = r4;
    }
}

// ---------------------------------------------------------------------------
// Pass B: 19-min over z fused with weighted-dice reduction + in-kernel
// finalize (last block computes the loss). Block = (ztile, y, b), 640 thr.
// ---------------------------------------------------------------------------
__global__ void __launch_bounds__(NTB, 2) minz_reduce_kernel(const float4* __restrict__ exy4,
                                                             const float4* __restrict__ pred4,
                                                             const float4* __restrict__ targ4,
                                                             float* __restrict__ out) {
    extern __shared__ float4 sm4[];
    float4* s4 = sm4;                         // HZ*SQ = 62720 B
    __shared__ float wsum[NTB / 32][3];

    const int tid = threadIdx.x;
    const int q   = tid % SQ;
    const int g   = tid / SQ;                 // 0..15
    const int z0  = blockIdx.x * TZ;
    const int y   = blockIdx.y;
    const int b   = blockIdx.z;
    const long long bbase4 = (long long)b * S * S * SQ;

    for (int i = tid; i < HZ * SQ; i += NTB) {
        const int r = i / SQ, qq = i % SQ;
        const int z = clampi(z0 - R + r, 0, S - 1);
        s4[i] = exy4[bbase4 + (long long)z * S * SQ + y * SQ + qq];
    }
    __syncthreads();

    float aI = 0.f, aP = 0.f, aT = 0.f;
    const float4* col = s4 + q;
    for (int gg = g; gg < TZ / 4; gg += 16) {
        const int o = 4 * gg;
        float4 p0 = f4min(col[(o + 3) * SQ],  col[(o + 4) * SQ]);
        float4 p1 = f4min(col[(o + 5) * SQ],  col[(o + 6) * SQ]);
        float4 p2 = f4min(col[(o + 7) * SQ],  col[(o + 8) * SQ]);
        float4 p3 = f4min(col[(o + 9) * SQ],  col[(o + 10) * SQ]);
        float4 p4 = f4min(col[(o + 11) * SQ], col[(o + 12) * SQ]);
        float4 p5 = f4min(col[(o + 13) * SQ], col[(o + 14) * SQ]);
        float4 p6 = f4min(col[(o + 15) * SQ], col[(o + 16) * SQ]);
        float4 p7 = f4min(col[(o + 17) * SQ], col[(o + 18) * SQ]);
        float4 core = f4min(f4min(f4min(p0, p1), f4min(p2, p3)),
                            f4min(f4min(p4, p5), f4min(p6, p7)));
        float4 a0 = col[(o + 0) * SQ],  a1 = col[(o + 1) * SQ];
        float4 a2 = col[(o + 2) * SQ];
        float4 b0 = col[(o + 19) * SQ], b1 = col[(o + 20) * SQ];
        float4 b2 = col[(o + 21) * SQ];
        float4 e[4];
        e[0] = f4min(f4min(a0, a1),   f4min(a2, core));
        e[1] = f4min(f4min(a1, a2),   f4min(core, b0));
        e[2] = f4min(f4min(a2, core), f4min(b0, b1));
        e[3] = f4min(f4min(core, b0), f4min(b1, b2));

#pragma unroll
        for (int j = 0; j < 4; ++j) {
            const long long idx4 = bbase4 + (long long)(z0 + o + j) * S * SQ + y * SQ + q;
            const float4 p = pred4[idx4];
            const float4 t = targ4[idx4];
            const float4 ev = e[j];
            float w, wp;
            w = fmaf(t.x - ev.x, 5.0f, 1.0f); wp = w * p.x;
            aI = fmaf(wp, t.x, aI); aP += wp; aT = fmaf(w, t.x, aT);
            w = fmaf(t.y - ev.y, 5.0f, 1.0f); wp = w * p.y;
            aI = fmaf(wp, t.y, aI); aP += wp; aT = fmaf(w, t.y, aT);
            w = fmaf(t.z - ev.z, 5.0f, 1.0f); wp = w * p.z;
            aI = fmaf(wp, t.z, aI); aP += wp; aT = fmaf(w, t.z, aT);
            w = fmaf(t.w - ev.w, 5.0f, 1.0f); wp = w * p.w;
            aI = fmaf(wp, t.w, aI); aP += wp; aT = fmaf(w, t.w, aT);
        }
    }

#pragma unroll
    for (int off = 16; off > 0; off >>= 1) {
        aI += __shfl_down_sync(0xFFFFFFFFu, aI, off);
        aP += __shfl_down_sync(0xFFFFFFFFu, aP, off);
        aT += __shfl_down_sync(0xFFFFFFFFu, aT, off);
    }
    const int wid = tid >> 5, lane = tid & 31;
    if (lane == 0) { wsum[wid][0] = aI; wsum[wid][1] = aP; wsum[wid][2] = aT; }
    __syncthreads();

    if (tid == 0) {
        double I = 0.0, P = 0.0, T = 0.0;
#pragma unroll
        for (int w = 0; w < NTB / 32; ++w) {
            I += (double)wsum[w][0];
            P += (double)wsum[w][1];
            T += (double)wsum[w][2];
        }
        atomicAdd(&g_acc[0], I);
        atomicAdd(&g_acc[1], P);
        atomicAdd(&g_acc[2], T);
        __threadfence();
        const unsigned int n = atomicAdd(&g_done, 1u);
        if (n == NBLOCKS_B - 1) {
            g_done = 0;   // reset for next graph replay (only this block alive)
            const double fI = atomicAdd(&g_acc[0], 0.0);
            const double fP = atomicAdd(&g_acc[1], 0.0);
            const double fT = atomicAdd(&g_acc[2], 0.0);
            const double dice = (2.0 * fI + 1e-5) / (fP + fT + 1e-5);
            out[0] = (float)(1.0 - dice);
        }
    }
}

// ---------------------------------------------------------------------------
extern "C" void kernel_launch(void* const* d_in, const int* in_sizes, int n_in,
                              void* d_out, int out_size) {
    const float4* pred = (const float4*)d_in[0];
    const float4* targ = (const float4*)d_in[1];
    float* out = (float*)d_out;
    (void)in_sizes; (void)n_in; (void)out_size;

    float* exy; cudaGetSymbolAddress((void**)&exy, g_exy);

    const int smemA = (HY + TY) * SQ * (int)sizeof(float4);  // 113920 B
    const int smemB = HZ * SQ * (int)sizeof(float4);         // 62720 B
    cudaFuncSetAttribute(minxy_kernel, cudaFuncAttributeMaxDynamicSharedMemorySize, smemA);
    cudaFuncSetAttribute(minz_reduce_kernel, cudaFuncAttributeMaxDynamicSharedMemorySize, smemB);

    dim3 gridA(S / TY, S, 4);   // (2, 160, 4)
    minxy_kernel<<<gridA, NTA, smemA>>>(targ, (float4*)exy);

    dim3 gridB(S / TZ, S, 4);   // (2, 160, 4)
    minz_reduce_kernel<<<gridB, NTB, smemB>>>((const float4*)exy, pred, targ, out);
}

// round 7
// speedup vs baseline: 1.2083x; 1.2083x over previous
#include <cuda_runtime.h>
#include <math.h>

#define S   160
#define SQ  40          // S/4 float4 quads per row
#define R   9           // 9x 3-erosion == one 19-window (clamped)
#define TY  32
#define TZ  32
#define NT  320         // 40 quads * 8 groups
#define NBLOCKS_B ((S / TZ) * S * 4)   // 3200

// Scratch (static __device__ = allowed; no allocation calls)
__device__ float        g_exy[4 * S * S * S];
__device__ double       g_acc[3];
__device__ unsigned int g_done;   // zero-init; last block resets it each replay

__device__ __forceinline__ int clampi(int v, int lo, int hi) {
    return v < lo ? lo : (v > hi ? hi : v);
}
__device__ __forceinline__ float4 f4min(float4 a, float4 b) {
    return make_float4(fminf(a.x, b.x), fminf(a.y, b.y),
                       fminf(a.z, b.z), fminf(a.w, b.w));
}

// ---------------------------------------------------------------------------
// Pass A: fused 19-min over y then x. Block = (ytile, z, b), 320 threads.
// smem: A[50][40] float4 raw rows, C[32][40] float4 y-min rows.
// Block (0,0,0) zeroes the accumulators (pass B reads them strictly later).
// ---------------------------------------------------------------------------
__global__ void __launch_bounds__(NT) minxy_kernel(const float4* __restrict__ in4,
                                                   float4* __restrict__ out4) {
    extern __shared__ float4 sm4[];
    float4* A = sm4;                 // 50*40
    float4* C = sm4 + 50 * SQ;       // 32*40

    const int tid = threadIdx.x;
    const int q   = tid % SQ;
    const int g   = tid / SQ;        // 0..7
    const int y0  = blockIdx.x * TY;
    const int z   = blockIdx.y;
    const int b   = blockIdx.z;
    const long long base4 = (long long)(b * S + z) * S * SQ;

    if (blockIdx.x == 0 && blockIdx.y == 0 && blockIdx.z == 0 && tid < 3)
        g_acc[tid] = 0.0;

    // Load 50 y-rows (clamped halo), float4-coalesced.
    for (int i = tid; i < 50 * SQ; i += NT) {
        const int r = i / SQ, qq = i % SQ;
        const int y = clampi(y0 - R + r, 0, S - 1);
        A[i] = in4[base4 + y * SQ + qq];
    }
    __syncthreads();

    // y-min: group of 4 outputs shares a 16-row tree-min core.
    {
        const int o = 4 * g;
        const float4* col = A + q;
        float4 p0 = f4min(col[(o + 3) * SQ],  col[(o + 4) * SQ]);
        float4 p1 = f4min(col[(o + 5) * SQ],  col[(o + 6) * SQ]);
        float4 p2 = f4min(col[(o + 7) * SQ],  col[(o + 8) * SQ]);
        float4 p3 = f4min(col[(o + 9) * SQ],  col[(o + 10) * SQ]);
        float4 p4 = f4min(col[(o + 11) * SQ], col[(o + 12) * SQ]);
        float4 p5 = f4min(col[(o + 13) * SQ], col[(o + 14) * SQ]);
        float4 p6 = f4min(col[(o + 15) * SQ], col[(o + 16) * SQ]);
        float4 p7 = f4min(col[(o + 17) * SQ], col[(o + 18) * SQ]);
        float4 core = f4min(f4min(f4min(p0, p1), f4min(p2, p3)),
                            f4min(f4min(p4, p5), f4min(p6, p7)));
        float4 a0 = col[(o + 0) * SQ],  a1 = col[(o + 1) * SQ];
        float4 a2 = col[(o + 2) * SQ];
        float4 b0 = col[(o + 19) * SQ], b1 = col[(o + 20) * SQ];
        float4 b2 = col[(o + 21) * SQ];
        C[(o + 0) * SQ + q] = f4min(f4min(a0, a1),   f4min(a2, core));
        C[(o + 1) * SQ + q] = f4min(f4min(a1, a2),   f4min(core, b0));
        C[(o + 2) * SQ + q] = f4min(f4min(a2, core), f4min(b0, b1));
        C[(o + 3) * SQ + q] = f4min(f4min(core, b0), f4min(b1, b2));
    }
    __syncthreads();

    // x-min: gather 7 float4 quads (quad-clamped, min-safe), tree core.
#pragma unroll
    for (int k = 0; k < 4; ++k) {
        const int i = tid + NT * k;          // 0..1279 exactly
        const int row = i / SQ, qq = i % SQ;
        float v[28];
#pragma unroll
        for (int dq = -3; dq <= 3; ++dq) {
            const float4 c = C[row * SQ + clampi(qq + dq, 0, SQ - 1)];
            const int o = (dq + 3) * 4;
            v[o] = c.x; v[o + 1] = c.y; v[o + 2] = c.z; v[o + 3] = c.w;
        }
        float t0 = fminf(v[6],  v[7]),  t1 = fminf(v[8],  v[9]);
        float t2 = fminf(v[10], v[11]), t3 = fminf(v[12], v[13]);
        float t4 = fminf(v[14], v[15]), t5 = fminf(v[16], v[17]);
        float t6 = fminf(v[18], v[19]), t7 = fminf(v[20], v[21]);
        float core = fminf(fminf(fminf(t0, t1), fminf(t2, t3)),
                           fminf(fminf(t4, t5), fminf(t6, t7)));
        float4 r4;
        r4.x = fminf(core, fminf(v[3],  fminf(v[4],  v[5])));
        r4.y = fminf(core, fminf(v[4],  fminf(v[5],  v[22])));
        r4.z = fminf(core, fminf(v[5],  fminf(v[22], v[23])));
        r4.w = fminf(core, fminf(v[22], fminf(v[23], v[24])));
        out4[base4 + (long long)(y0 + row) * SQ + qq] = r4;
    }
}

// ---------------------------------------------------------------------------
// Pass B: 19-min over z fused with the weighted-dice reduction; the last
// block finalizes the loss in-kernel.
// ---------------------------------------------------------------------------
__global__ void __launch_bounds__(NT) minz_reduce_kernel(const float4* __restrict__ exy4,
                                                         const float4* __restrict__ pred4,
                                                         const float4* __restrict__ targ4,
                                                         float* __restrict__ out) {
    __shared__ float4 s4[50 * SQ];           // 32000 B
    __shared__ float  wsum[NT / 32][3];

    const int tid = threadIdx.x;
    const int q   = tid % SQ;
    const int g   = tid / SQ;                // 0..7
    const int o   = 4 * g;
    const int z0  = blockIdx.x * TZ;
    const int y   = blockIdx.y;
    const int b   = blockIdx.z;
    const long long bbase4 = (long long)b * S * S * SQ;

    for (int i = tid; i < 50 * SQ; i += NT) {
        const int r = i / SQ, qq = i % SQ;
        const int z = clampi(z0 - R + r, 0, S - 1);
        s4[i] = exy4[bbase4 + (long long)z * S * SQ + y * SQ + qq];
    }
    __syncthreads();

    const float4* col = s4 + q;
    float4 p0 = f4min(col[(o + 3) * SQ],  col[(o + 4) * SQ]);
    float4 p1 = f4min(col[(o + 5) * SQ],  col[(o + 6) * SQ]);
    float4 p2 = f4min(col[(o + 7) * SQ],  col[(o + 8) * SQ]);
    float4 p3 = f4min(col[(o + 9) * SQ],  col[(o + 10) * SQ]);
    float4 p4 = f4min(col[(o + 11) * SQ], col[(o + 12) * SQ]);
    float4 p5 = f4min(col[(o + 13) * SQ], col[(o + 14) * SQ]);
    float4 p6 = f4min(col[(o + 15) * SQ], col[(o + 16) * SQ]);
    float4 p7 = f4min(col[(o + 17) * SQ], col[(o + 18) * SQ]);
    float4 core = f4min(f4min(f4min(p0, p1), f4min(p2, p3)),
                        f4min(f4min(p4, p5), f4min(p6, p7)));
    float4 a0 = col[(o + 0) * SQ],  a1 = col[(o + 1) * SQ];
    float4 a2 = col[(o + 2) * SQ];
    float4 b0 = col[(o + 19) * SQ], b1 = col[(o + 20) * SQ];
    float4 b2 = col[(o + 21) * SQ];
    float4 e[4];
    e[0] = f4min(f4min(a0, a1),   f4min(a2, core));
    e[1] = f4min(f4min(a1, a2),   f4min(core, b0));
    e[2] = f4min(f4min(a2, core), f4min(b0, b1));
    e[3] = f4min(f4min(core, b0), f4min(b1, b2));

    float aI = 0.f, aP = 0.f, aT = 0.f;
#pragma unroll
    for (int j = 0; j < 4; ++j) {
        const long long idx4 = bbase4 + (long long)(z0 + o + j) * S * SQ + y * SQ + q;
        const float4 p = pred4[idx4];
        const float4 t = targ4[idx4];
        const float4 ev = e[j];
        float w, wp;
        w = fmaf(t.x - ev.x, 5.0f, 1.0f); wp = w * p.x;
        aI = fmaf(wp, t.x, aI); aP += wp; aT = fmaf(w, t.x, aT);
        w = fmaf(t.y - ev.y, 5.0f, 1.0f); wp = w * p.y;
        aI = fmaf(wp, t.y, aI); aP += wp; aT = fmaf(w, t.y, aT);
        w = fmaf(t.z - ev.z, 5.0f, 1.0f); wp = w * p.z;
        aI = fmaf(wp, t.z, aI); aP += wp; aT = fmaf(w, t.z, aT);
        w = fmaf(t.w - ev.w, 5.0f, 1.0f); wp = w * p.w;
        aI = fmaf(wp, t.w, aI); aP += wp; aT = fmaf(w, t.w, aT);
    }

#pragma unroll
    for (int off = 16; off > 0; off >>= 1) {
        aI += __shfl_down_sync(0xFFFFFFFFu, aI, off);
        aP += __shfl_down_sync(0xFFFFFFFFu, aP, off);
        aT += __shfl_down_sync(0xFFFFFFFFu, aT, off);
    }
    const int wid = tid >> 5, lane = tid & 31;
    if (lane == 0) { wsum[wid][0] = aI; wsum[wid][1] = aP; wsum[wid][2] = aT; }
    __syncthreads();

    if (tid == 0) {
        double I = 0.0, P = 0.0, T = 0.0;
#pragma unroll
        for (int w = 0; w < NT / 32; ++w) {
            I += (double)wsum[w][0];
            P += (double)wsum[w][1];
            T += (double)wsum[w][2];
        }
        atomicAdd(&g_acc[0], I);
        atomicAdd(&g_acc[1], P);
        atomicAdd(&g_acc[2], T);
        __threadfence();
        const unsigned int n = atomicAdd(&g_done, 1u);
        if (n == NBLOCKS_B - 1) {
            g_done = 0;   // reset for next graph replay (only this block alive)
            const double fI = atomicAdd(&g_acc[0], 0.0);
            const double fP = atomicAdd(&g_acc[1], 0.0);
            const double fT = atomicAdd(&g_acc[2], 0.0);
            const double dice = (2.0 * fI + 1e-5) / (fP + fT + 1e-5);
            out[0] = (float)(1.0 - dice);
        }
    }
}

// ---------------------------------------------------------------------------
extern "C" void kernel_launch(void* const* d_in, const int* in_sizes, int n_in,
                              void* d_out, int out_size) {
    const float4* pred = (const float4*)d_in[0];
    const float4* targ = (const float4*)d_in[1];
    float* out = (float*)d_out;
    (void)in_sizes; (void)n_in; (void)out_size;

    float* exy; cudaGetSymbolAddress((void**)&exy, g_exy);

    const int smemA = (50 + TY) * SQ * (int)sizeof(float4);   // 52480 B
    cudaFuncSetAttribute(minxy_kernel, cudaFuncAttributeMaxDynamicSharedMemorySize, smemA);

    dim3 gridA(S / TY, S, 4);    // (5, 160, 4)
    minxy_kernel<<<gridA, NT, smemA>>>(targ, (float4*)exy);

    dim3 gridB(S / TZ, S, 4);    // (5, 160, 4)
    minz_reduce_kernel<<<gridB, NT>>>((const float4*)exy, pred, targ, out);
}

// round 10
// speedup vs baseline: 1.4146x; 1.1707x over previous
#include <cuda_runtime.h>
#include <cuda_fp16.h>
#include <math.h>

#define S   160
#define SQ  40          // S/4 quads per row (quad = 4 elems)
#define R   9           // 9x 3-erosion == one 19-window (clamped)
#define TY  32
#define TZ  32
#define NT  320         // 40 quads * 8 groups
#define NBLOCKS_B ((S / TZ) * S * 4)   // 3200
#define NQUADS (4 * S * S * SQ)        // total fp16-quad (uint2) count

// Scratch: eroded-xy field stored as packed fp16 quads. Declared as uint2 so
// 8-byte alignment of every access is guaranteed by the type itself.
// (min is monotonic => rounding after xy-min and before z-min equals rounding
// the true eroded field once.)
__device__ uint2        g_exy[NQUADS];
__device__ double       g_acc[3];
__device__ unsigned int g_done;   // zero-init; last block resets it each replay

__device__ __forceinline__ int clampi(int v, int lo, int hi) {
    return v < lo ? lo : (v > hi ? hi : v);
}
__device__ __forceinline__ float4 f4min(float4 a, float4 b) {
    return make_float4(fminf(a.x, b.x), fminf(a.y, b.y),
                       fminf(a.z, b.z), fminf(a.w, b.w));
}

// 4 halves (one quad) packed in a uint2
struct H4 { __half2 a, b; };
__device__ __forceinline__ H4 h4min(H4 x, H4 y) {
    H4 r; r.a = __hmin2(x.a, y.a); r.b = __hmin2(x.b, y.b); return r;
}
__device__ __forceinline__ H4 h4_from_u2(uint2 u) {
    H4 r;
    r.a = __halves2half2(__ushort_as_half((unsigned short)(u.x & 0xFFFFu)),
                         __ushort_as_half((unsigned short)(u.x >> 16)));
    r.b = __halves2half2(__ushort_as_half((unsigned short)(u.y & 0xFFFFu)),
                         __ushort_as_half((unsigned short)(u.y >> 16)));
    return r;
}

// ---------------------------------------------------------------------------
// Pass A: fused 19-min over y then x. Block = (ytile, z, b), 320 threads.
// smem: A[50][40] float4 raw rows, C[32][40] float4 y-min rows.
// Output written as fp16 quads (uint2). Block (0,0,0) zeroes accumulators.
// ---------------------------------------------------------------------------
__global__ void __launch_bounds__(NT) minxy_kernel(const float4* __restrict__ in4,
                                                   uint2* __restrict__ outh) {
    extern __shared__ float4 sm4[];
    float4* A = sm4;                 // 50*40
    float4* C = sm4 + 50 * SQ;       // 32*40

    const int tid = threadIdx.x;
    const int q   = tid % SQ;
    const int g   = tid / SQ;        // 0..7
    const int y0  = blockIdx.x * TY;
    const int z   = blockIdx.y;
    const int b   = blockIdx.z;
    const long long base4 = (long long)(b * S + z) * S * SQ;

    if (blockIdx.x == 0 && blockIdx.y == 0 && blockIdx.z == 0 && tid < 3)
        g_acc[tid] = 0.0;

    // Load 50 y-rows (clamped halo), float4-coalesced.
    for (int i = tid; i < 50 * SQ; i += NT) {
        const int r = i / SQ, qq = i % SQ;
        const int y = clampi(y0 - R + r, 0, S - 1);
        A[i] = in4[base4 + y * SQ + qq];
    }
    __syncthreads();

    // y-min: group of 4 outputs shares a 16-row tree-min core.
    {
        const int o = 4 * g;
        const float4* col = A + q;
        float4 p0 = f4min(col[(o + 3) * SQ],  col[(o + 4) * SQ]);
        float4 p1 = f4min(col[(o + 5) * SQ],  col[(o + 6) * SQ]);
        float4 p2 = f4min(col[(o + 7) * SQ],  col[(o + 8) * SQ]);
        float4 p3 = f4min(col[(o + 9) * SQ],  col[(o + 10) * SQ]);
        float4 p4 = f4min(col[(o + 11) * SQ], col[(o + 12) * SQ]);
        float4 p5 = f4min(col[(o + 13) * SQ], col[(o + 14) * SQ]);
        float4 p6 = f4min(col[(o + 15) * SQ], col[(o + 16) * SQ]);
        float4 p7 = f4min(col[(o + 17) * SQ], col[(o + 18) * SQ]);
        float4 core = f4min(f4min(f4min(p0, p1), f4min(p2, p3)),
                            f4min(f4min(p4, p5), f4min(p6, p7)));
        float4 a0 = col[(o + 0) * SQ],  a1 = col[(o + 1) * SQ];
        float4 a2 = col[(o + 2) * SQ];
        float4 b0 = col[(o + 19) * SQ], b1 = col[(o + 20) * SQ];
        float4 b2 = col[(o + 21) * SQ];
        C[(o + 0) * SQ + q] = f4min(f4min(a0, a1),   f4min(a2, core));
        C[(o + 1) * SQ + q] = f4min(f4min(a1, a2),   f4min(core, b0));
        C[(o + 2) * SQ + q] = f4min(f4min(a2, core), f4min(b0, b1));
        C[(o + 3) * SQ + q] = f4min(f4min(core, b0), f4min(b1, b2));
    }
    __syncthreads();

    // x-min: gather 7 float4 quads (quad-clamped, min-safe), tree core,
    // then round once to fp16 and store as uint2.
#pragma unroll
    for (int k = 0; k < 4; ++k) {
        const int i = tid + NT * k;          // 0..1279 exactly
        const int row = i / SQ, qq = i % SQ;
        float v[28];
#pragma unroll
        for (int dq = -3; dq <= 3; ++dq) {
            const float4 c = C[row * SQ + clampi(qq + dq, 0, SQ - 1)];
            const int o = (dq + 3) * 4;
            v[o] = c.x; v[o + 1] = c.y; v[o + 2] = c.z; v[o + 3] = c.w;
        }
        float t0 = fminf(v[6],  v[7]),  t1 = fminf(v[8],  v[9]);
        float t2 = fminf(v[10], v[11]), t3 = fminf(v[12], v[13]);
        float t4 = fminf(v[14], v[15]), t5 = fminf(v[16], v[17]);
        float t6 = fminf(v[18], v[19]), t7 = fminf(v[20], v[21]);
        float core = fminf(fminf(fminf(t0, t1), fminf(t2, t3)),
                           fminf(fminf(t4, t5), fminf(t6, t7)));
        float4 r4;
        r4.x = fminf(core, fminf(v[3],  fminf(v[4],  v[5])));
        r4.y = fminf(core, fminf(v[4],  fminf(v[5],  v[22])));
        r4.z = fminf(core, fminf(v[5],  fminf(v[22], v[23])));
        r4.w = fminf(core, fminf(v[22], fminf(v[23], v[24])));

        const __half2 h01 = __floats2half2_rn(r4.x, r4.y);
        const __half2 h23 = __floats2half2_rn(r4.z, r4.w);
        uint2 u;
        u.x = ((unsigned)__half_as_ushort(__high2half(h01)) << 16) |
               (unsigned)__half_as_ushort(__low2half(h01));
        u.y = ((unsigned)__half_as_ushort(__high2half(h23)) << 16) |
               (unsigned)__half_as_ushort(__low2half(h23));
        outh[base4 + (long long)(y0 + row) * SQ + qq] = u;
    }
}

// ---------------------------------------------------------------------------
// Pass B: 19-min over z (fp16, __hmin2 tree) fused with the weighted-dice
// reduction; the last block finalizes the loss in-kernel.
// ---------------------------------------------------------------------------
__global__ void __launch_bounds__(NT) minz_reduce_kernel(const uint2* __restrict__ exyh,
                                                         const float4* __restrict__ pred4,
                                                         const float4* __restrict__ targ4,
                                                         float* __restrict__ out) {
    __shared__ uint2 s2[50 * SQ];            // 16000 B (half quads)
    __shared__ float wsum[NT / 32][3];

    const int tid = threadIdx.x;
    const int q   = tid % SQ;
    const int g   = tid / SQ;                // 0..7
    const int o   = 4 * g;
    const int z0  = blockIdx.x * TZ;
    const int y   = blockIdx.y;
    const int b   = blockIdx.z;
    const long long bbase4 = (long long)b * S * S * SQ;

    for (int i = tid; i < 50 * SQ; i += NT) {
        const int r = i / SQ, qq = i % SQ;
        const int z = clampi(z0 - R + r, 0, S - 1);
        s2[i] = exyh[bbase4 + (long long)z * S * SQ + y * SQ + qq];
    }
    __syncthreads();

    const uint2* col = s2 + q;
    H4 p0 = h4min(h4_from_u2(col[(o + 3) * SQ]),  h4_from_u2(col[(o + 4) * SQ]));
    H4 p1 = h4min(h4_from_u2(col[(o + 5) * SQ]),  h4_from_u2(col[(o + 6) * SQ]));
    H4 p2 = h4min(h4_from_u2(col[(o + 7) * SQ]),  h4_from_u2(col[(o + 8) * SQ]));
    H4 p3 = h4min(h4_from_u2(col[(o + 9) * SQ]),  h4_from_u2(col[(o + 10) * SQ]));
    H4 p4 = h4min(h4_from_u2(col[(o + 11) * SQ]), h4_from_u2(col[(o + 12) * SQ]));
    H4 p5 = h4min(h4_from_u2(col[(o + 13) * SQ]), h4_from_u2(col[(o + 14) * SQ]));
    H4 p6 = h4min(h4_from_u2(col[(o + 15) * SQ]), h4_from_u2(col[(o + 16) * SQ]));
    H4 p7 = h4min(h4_from_u2(col[(o + 17) * SQ]), h4_from_u2(col[(o + 18) * SQ]));
    H4 core = h4min(h4min(h4min(p0, p1), h4min(p2, p3)),
                    h4min(h4min(p4, p5), h4min(p6, p7)));
    H4 a0 = h4_from_u2(col[(o + 0) * SQ]),  a1 = h4_from_u2(col[(o + 1) * SQ]);
    H4 a2 = h4_from_u2(col[(o + 2) * SQ]);
    H4 b0 = h4_from_u2(col[(o + 19) * SQ]), b1 = h4_from_u2(col[(o + 20) * SQ]);
    H4 b2 = h4_from_u2(col[(o + 21) * SQ]);
    H4 e[4];
    e[0] = h4min(h4min(a0, a1),   h4min(a2, core));
    e[1] = h4min(h4min(a1, a2),   h4min(core, b0));
    e[2] = h4min(h4min(a2, core), h4min(b0, b1));
    e[3] = h4min(h4min(core, b0), h4min(b1, b2));

    float aI = 0.f, aP = 0.f, aT = 0.f;
#pragma unroll
    for (int j = 0; j < 4; ++j) {
        const long long idx4 = bbase4 + (long long)(z0 + o + j) * S * SQ + y * SQ + q;
        const float4 p = pred4[idx4];
        const float4 t = targ4[idx4];
        const float2 elo = __half22float2(e[j].a);
        const float2 ehi = __half22float2(e[j].b);
        float w, wp;
        w = fmaf(t.x - elo.x, 5.0f, 1.0f); wp = w * p.x;
        aI = fmaf(wp, t.x, aI); aP += wp; aT = fmaf(w, t.x, aT);
        w = fmaf(t.y - elo.y, 5.0f, 1.0f); wp = w * p.y;
        aI = fmaf(wp, t.y, aI); aP += wp; aT = fmaf(w, t.y, aT);
        w = fmaf(t.z - ehi.x, 5.0f, 1.0f); wp = w * p.z;
        aI = fmaf(wp, t.z, aI); aP += wp; aT = fmaf(w, t.z, aT);
        w = fmaf(t.w - ehi.y, 5.0f, 1.0f); wp = w * p.w;
        aI = fmaf(wp, t.w, aI); aP += wp; aT = fmaf(w, t.w, aT);
    }

#pragma unroll
    for (int off = 16; off > 0; off >>= 1) {
        aI += __shfl_down_sync(0xFFFFFFFFu, aI, off);
        aP += __shfl_down_sync(0xFFFFFFFFu, aP, off);
        aT += __shfl_down_sync(0xFFFFFFFFu, aT, off);
    }
    const int wid = tid >> 5, lane = tid & 31;
    if (lane == 0) { wsum[wid][0] = aI; wsum[wid][1] = aP; wsum[wid][2] = aT; }
    __syncthreads();

    if (tid == 0) {
        double I = 0.0, P = 0.0, T = 0.0;
#pragma unroll
        for (int w = 0; w < NT / 32; ++w) {
            I += (double)wsum[w][0];
            P += (double)wsum[w][1];
            T += (double)wsum[w][2];
        }
        atomicAdd(&g_acc[0], I);
        atomicAdd(&g_acc[1], P);
        atomicAdd(&g_acc[2], T);
        __threadfence();
        const unsigned int n = atomicAdd(&g_done, 1u);
        if (n == NBLOCKS_B - 1) {
            g_done = 0;   // reset for next graph replay (only this block alive)
            const double fI = atomicAdd(&g_acc[0], 0.0);
            const double fP = atomicAdd(&g_acc[1], 0.0);
            const double fT = atomicAdd(&g_acc[2], 0.0);
            const double dice = (2.0 * fI + 1e-5) / (fP + fT + 1e-5);
            out[0] = (float)(1.0 - dice);
        }
    }
}

// ---------------------------------------------------------------------------
extern "C" void kernel_launch(void* const* d_in, const int* in_sizes, int n_in,
                              void* d_out, int out_size) {
    const float4* pred = (const float4*)d_in[0];
    const float4* targ = (const float4*)d_in[1];
    float* out = (float*)d_out;
    (void)in_sizes; (void)n_in; (void)out_size;

    uint2* exy; cudaGetSymbolAddress((void**)&exy, g_exy);

    const int smemA = (50 + TY) * SQ * (int)sizeof(float4);   // 52480 B
    cudaFuncSetAttribute(minxy_kernel, cudaFuncAttributeMaxDynamicSharedMemorySize, smemA);

    dim3 gridA(S / TY, S, 4);    // (5, 160, 4)
    minxy_kernel<<<gridA, NT, smemA>>>(targ, exy);

    dim3 gridB(S / TZ, S, 4);    // (5, 160, 4)
    minz_reduce_kernel<<<gridB, NT>>>(exy, pred, targ, out);
}

// round 11
// speedup vs baseline: 1.6104x; 1.1384x over previous
#include <cuda_runtime.h>
#include <cuda_fp16.h>
#include <math.h>

#define S   160
#define SQ  40          // S/4 quads per row (quad = 4 elems)
#define R   9           // 9x 3-erosion == one 19-window (clamped)
#define TY  32
#define TZ  32
#define NT  320         // 40 quads * 8 groups
#define NBLOCKS_B ((S / TZ) * S * 4)   // 3200
#define NQUADS (4 * S * S * SQ)        // total fp16-quad (uint2) count

// Scratch: eroded-xy field as packed fp16 quads (uint2 => 8B alignment
// guaranteed by type). min is monotonic => rounding target to fp16 before
// the min cascade equals rounding the true eroded field once at the end.
__device__ uint2        g_exy[NQUADS];
__device__ double       g_acc[3];
__device__ unsigned int g_done;   // zero-init; last block resets it each replay

__device__ __forceinline__ int clampi(int v, int lo, int hi) {
    return v < lo ? lo : (v > hi ? hi : v);
}

// ---- fp16 helpers -------------------------------------------------------
__device__ __forceinline__ unsigned h2_to_u(__half2 h) {
    return ((unsigned)__half_as_ushort(__high2half(h)) << 16) |
            (unsigned)__half_as_ushort(__low2half(h));
}
__device__ __forceinline__ __half2 u_to_h2(unsigned u) {
    return __halves2half2(__ushort_as_half((unsigned short)(u & 0xFFFFu)),
                          __ushort_as_half((unsigned short)(u >> 16)));
}
__device__ __forceinline__ unsigned umin2(unsigned a, unsigned b) {
    return h2_to_u(__hmin2(u_to_h2(a), u_to_h2(b)));
}
struct H4 { __half2 a, b; };
__device__ __forceinline__ H4 h4min(H4 x, H4 y) {
    H4 r; r.a = __hmin2(x.a, y.a); r.b = __hmin2(x.b, y.b); return r;
}
__device__ __forceinline__ H4 h4_from_u2(uint2 u) {
    H4 r; r.a = u_to_h2(u.x); r.b = u_to_h2(u.y); return r;
}
__device__ __forceinline__ uint2 u2_from_h4(H4 h) {
    uint2 u; u.x = h2_to_u(h.a); u.y = h2_to_u(h.b); return u;
}

// ---------------------------------------------------------------------------
// Pass A: fused 19-min over y then x, entirely in fp16.
// Block = (ytile, z, b), 320 threads (q = tid%40, g = tid/40).
// smem: A[50][40] half-quads (16000 B), C[32][40] half-quads (10240 B).
// ---------------------------------------------------------------------------
__global__ void __launch_bounds__(NT) minxy_kernel(const float4* __restrict__ in4,
                                                   uint2* __restrict__ outh) {
    extern __shared__ uint2 smu[];
    uint2* A = smu;                  // 50*40
    uint2* C = smu + 50 * SQ;        // 32*40

    const int tid = threadIdx.x;
    const int q   = tid % SQ;
    const int g   = tid / SQ;        // 0..7
    const int y0  = blockIdx.x * TY;
    const int z   = blockIdx.y;
    const int b   = blockIdx.z;
    const long long base4 = (long long)(b * S + z) * S * SQ;

    if (blockIdx.x == 0 && blockIdx.y == 0 && blockIdx.z == 0 && tid < 3)
        g_acc[tid] = 0.0;

    // Load 50 y-rows (clamped halo), convert fp32->fp16 at load.
    for (int i = tid; i < 50 * SQ; i += NT) {
        const int r = i / SQ, qq = i % SQ;
        const int y = clampi(y0 - R + r, 0, S - 1);
        const float4 f = in4[base4 + y * SQ + qq];
        uint2 u;
        u.x = h2_to_u(__floats2half2_rn(f.x, f.y));
        u.y = h2_to_u(__floats2half2_rn(f.z, f.w));
        A[i] = u;
    }
    __syncthreads();

    // y-min: group of 4 outputs shares a 16-row tree-min core (fp16 SIMD).
    {
        const int o = 4 * g;
        const uint2* col = A + q;
        H4 p0 = h4min(h4_from_u2(col[(o + 3) * SQ]),  h4_from_u2(col[(o + 4) * SQ]));
        H4 p1 = h4min(h4_from_u2(col[(o + 5) * SQ]),  h4_from_u2(col[(o + 6) * SQ]));
        H4 p2 = h4min(h4_from_u2(col[(o + 7) * SQ]),  h4_from_u2(col[(o + 8) * SQ]));
        H4 p3 = h4min(h4_from_u2(col[(o + 9) * SQ]),  h4_from_u2(col[(o + 10) * SQ]));
        H4 p4 = h4min(h4_from_u2(col[(o + 11) * SQ]), h4_from_u2(col[(o + 12) * SQ]));
        H4 p5 = h4min(h4_from_u2(col[(o + 13) * SQ]), h4_from_u2(col[(o + 14) * SQ]));
        H4 p6 = h4min(h4_from_u2(col[(o + 15) * SQ]), h4_from_u2(col[(o + 16) * SQ]));
        H4 p7 = h4min(h4_from_u2(col[(o + 17) * SQ]), h4_from_u2(col[(o + 18) * SQ]));
        H4 core = h4min(h4min(h4min(p0, p1), h4min(p2, p3)),
                        h4min(h4min(p4, p5), h4min(p6, p7)));
        H4 a0 = h4_from_u2(col[(o + 0) * SQ]),  a1 = h4_from_u2(col[(o + 1) * SQ]);
        H4 a2 = h4_from_u2(col[(o + 2) * SQ]);
        H4 b0 = h4_from_u2(col[(o + 19) * SQ]), b1 = h4_from_u2(col[(o + 20) * SQ]);
        H4 b2 = h4_from_u2(col[(o + 21) * SQ]);
        C[(o + 0) * SQ + q] = u2_from_h4(h4min(h4min(a0, a1),   h4min(a2, core)));
        C[(o + 1) * SQ + q] = u2_from_h4(h4min(h4min(a1, a2),   h4min(core, b0)));
        C[(o + 2) * SQ + q] = u2_from_h4(h4min(h4min(a2, core), h4min(b0, b1)));
        C[(o + 3) * SQ + q] = u2_from_h4(h4min(h4min(core, b0), h4min(b1, b2)));
    }
    __syncthreads();

    // x-min: SIMD-paired windows. Gather 7 half-quads (quad-clamped, min-safe)
    // covering elements t = -12..15 relative to the output quad start.
    // h[i] (uint32 of 2 halves) covers t = 2i-12, 2i-11.
    // Slice S[d] = (e[d], e[d+1]); even d aligned, odd d via one PRMT.
    // (W0,W1) = min S[-9..9];  (W2,W3) = min S[-7..11]; shared core S[-7..9].
#pragma unroll
    for (int k = 0; k < 4; ++k) {
        const int i = tid + NT * k;          // 0..1279 exactly
        const int row = i / SQ, qq = i % SQ;
        unsigned h[14];
#pragma unroll
        for (int dq = -3; dq <= 3; ++dq) {
            const uint2 c = C[row * SQ + clampi(qq + dq, 0, SQ - 1)];
            h[2 * (dq + 3)]     = c.x;
            h[2 * (dq + 3) + 1] = c.y;
        }
        // s[j] = S[d] with d = j - 9, j = 0..20
        unsigned s[21];
#pragma unroll
        for (int j = 0; j < 21; ++j) {
            const int d = j - 9;
            if ((d & 1) == 0) {
                s[j] = h[(d + 12) >> 1];                       // aligned
            } else {
                s[j] = __byte_perm(h[(d + 11) >> 1], h[(d + 13) >> 1], 0x5432);
            }
        }
        // core = min of s[2..18] (17 slices), tree depth 5
        unsigned c0 = umin2(s[2],  s[3]),  c1 = umin2(s[4],  s[5]);
        unsigned c2 = umin2(s[6],  s[7]),  c3 = umin2(s[8],  s[9]);
        unsigned c4 = umin2(s[10], s[11]), c5 = umin2(s[12], s[13]);
        unsigned c6 = umin2(s[14], s[15]), c7 = umin2(s[16], s[17]);
        unsigned d0 = umin2(c0, c1), d1 = umin2(c2, c3);
        unsigned d2 = umin2(c4, c5), d3 = umin2(c6, c7);
        unsigned core = umin2(umin2(umin2(d0, d1), umin2(d2, d3)), s[18]);
        uint2 r;
        r.x = umin2(umin2(s[0],  s[1]),  core);   // (W0, W1)
        r.y = umin2(umin2(s[19], s[20]), core);   // (W2, W3)
        outh[base4 + (long long)(y0 + row) * SQ + qq] = r;
    }
}

// ---------------------------------------------------------------------------
// Pass B: 19-min over z (fp16 __hmin2 tree) fused with the weighted-dice
// reduction; the last block finalizes the loss in-kernel. (Unchanged from R9.)
// ---------------------------------------------------------------------------
__global__ void __launch_bounds__(NT) minz_reduce_kernel(const uint2* __restrict__ exyh,
                                                         const float4* __restrict__ pred4,
                                                         const float4* __restrict__ targ4,
                                                         float* __restrict__ out) {
    __shared__ uint2 s2[50 * SQ];            // 16000 B
    __shared__ float wsum[NT / 32][3];

    const int tid = threadIdx.x;
    const int q   = tid % SQ;
    const int g   = tid / SQ;                // 0..7
    const int o   = 4 * g;
    const int z0  = blockIdx.x * TZ;
    const int y   = blockIdx.y;
    const int b   = blockIdx.z;
    const long long bbase4 = (long long)b * S * S * SQ;

    for (int i = tid; i < 50 * SQ; i += NT) {
        const int r = i / SQ, qq = i % SQ;
        const int z = clampi(z0 - R + r, 0, S - 1);
        s2[i] = exyh[bbase4 + (long long)z * S * SQ + y * SQ + qq];
    }
    __syncthreads();

    const uint2* col = s2 + q;
    H4 p0 = h4min(h4_from_u2(col[(o + 3) * SQ]),  h4_from_u2(col[(o + 4) * SQ]));
    H4 p1 = h4min(h4_from_u2(col[(o + 5) * SQ]),  h4_from_u2(col[(o + 6) * SQ]));
    H4 p2 = h4min(h4_from_u2(col[(o + 7) * SQ]),  h4_from_u2(col[(o + 8) * SQ]));
    H4 p3 = h4min(h4_from_u2(col[(o + 9) * SQ]),  h4_from_u2(col[(o + 10) * SQ]));
    H4 p4 = h4min(h4_from_u2(col[(o + 11) * SQ]), h4_from_u2(col[(o + 12) * SQ]));
    H4 p5 = h4min(h4_from_u2(col[(o + 13) * SQ]), h4_from_u2(col[(o + 14) * SQ]));
    H4 p6 = h4min(h4_from_u2(col[(o + 15) * SQ]), h4_from_u2(col[(o + 16) * SQ]));
    H4 p7 = h4min(h4_from_u2(col[(o + 17) * SQ]), h4_from_u2(col[(o + 18) * SQ]));
    H4 core = h4min(h4min(h4min(p0, p1), h4min(p2, p3)),
                    h4min(h4min(p4, p5), h4min(p6, p7)));
    H4 a0 = h4_from_u2(col[(o + 0) * SQ]),  a1 = h4_from_u2(col[(o + 1) * SQ]);
    H4 a2 = h4_from_u2(col[(o + 2) * SQ]);
    H4 b0 = h4_from_u2(col[(o + 19) * SQ]), b1 = h4_from_u2(col[(o + 20) * SQ]);
    H4 b2 = h4_from_u2(col[(o + 21) * SQ]);
    H4 e[4];
    e[0] = h4min(h4min(a0, a1),   h4min(a2, core));
    e[1] = h4min(h4min(a1, a2),   h4min(core, b0));
    e[2] = h4min(h4min(a2, core), h4min(b0, b1));
    e[3] = h4min(h4min(core, b0), h4min(b1, b2));

    float aI = 0.f, aP = 0.f, aT = 0.f;
#pragma unroll
    for (int j = 0; j < 4; ++j) {
        const long long idx4 = bbase4 + (long long)(z0 + o + j) * S * SQ + y * SQ + q;
        const float4 p = pred4[idx4];
        const float4 t = targ4[idx4];
        const float2 elo = __half22float2(e[j].a);
        const float2 ehi = __half22float2(e[j].b);
        float w, wp;
        w = fmaf(t.x - elo.x, 5.0f, 1.0f); wp = w * p.x;
        aI = fmaf(wp, t.x, aI); aP += wp; aT = fmaf(w, t.x, aT);
        w = fmaf(t.y - elo.y, 5.0f, 1.0f); wp = w * p.y;
        aI = fmaf(wp, t.y, aI); aP += wp; aT = fmaf(w, t.y, aT);
        w = fmaf(t.z - ehi.x, 5.0f, 1.0f); wp = w * p.z;
        aI = fmaf(wp, t.z, aI); aP += wp; aT = fmaf(w, t.z, aT);
        w = fmaf(t.w - ehi.y, 5.0f, 1.0f); wp = w * p.w;
        aI = fmaf(wp, t.w, aI); aP += wp; aT = fmaf(w, t.w, aT);
    }

#pragma unroll
    for (int off = 16; off > 0; off >>= 1) {
        aI += __shfl_down_sync(0xFFFFFFFFu, aI, off);
        aP += __shfl_down_sync(0xFFFFFFFFu, aP, off);
        aT += __shfl_down_sync(0xFFFFFFFFu, aT, off);
    }
    const int wid = tid >> 5, lane = tid & 31;
    if (lane == 0) { wsum[wid][0] = aI; wsum[wid][1] = aP; wsum[wid][2] = aT; }
    __syncthreads();

    if (tid == 0) {
        double I = 0.0, P = 0.0, T = 0.0;
#pragma unroll
        for (int w = 0; w < NT / 32; ++w) {
            I += (double)wsum[w][0];
            P += (double)wsum[w][1];
            T += (double)wsum[w][2];
        }
        atomicAdd(&g_acc[0], I);
        atomicAdd(&g_acc[1], P);
        atomicAdd(&g_acc[2], T);
        __threadfence();
        const unsigned int n = atomicAdd(&g_done, 1u);
        if (n == NBLOCKS_B - 1) {
            g_done = 0;   // reset for next graph replay (only this block alive)
            const double fI = atomicAdd(&g_acc[0], 0.0);
            const double fP = atomicAdd(&g_acc[1], 0.0);
            const double fT = atomicAdd(&g_acc[2], 0.0);
            const double dice = (2.0 * fI + 1e-5) / (fP + fT + 1e-5);
            out[0] = (float)(1.0 - dice);
        }
    }
}

// ---------------------------------------------------------------------------
extern "C" void kernel_launch(void* const* d_in, const int* in_sizes, int n_in,
                              void* d_out, int out_size) {
    const float4* pred = (const float4*)d_in[0];
    const float4* targ = (const float4*)d_in[1];
    float* out = (float*)d_out;
    (void)in_sizes; (void)n_in; (void)out_size;

    uint2* exy; cudaGetSymbolAddress((void**)&exy, g_exy);

    const int smemA = (50 + TY) * SQ * (int)sizeof(uint2);   // 26240 B
    cudaFuncSetAttribute(minxy_kernel, cudaFuncAttributeMaxDynamicSharedMemorySize, smemA);

    dim3 gridA(S / TY, S, 4);    // (5, 160, 4)
    minxy_kernel<<<gridA, NT, smemA>>>(targ, exy);

    dim3 gridB(S / TZ, S, 4);    // (5, 160, 4)
    minz_reduce_kernel<<<gridB, NT>>>(exy, pred, targ, out);
}